// round 14
// baseline (speedup 1.0000x reference)
#include <cuda_runtime.h>
#include <cuda_fp16.h>
#include <math.h>

#define NN 50000
#define EE 600000
#define DD 128
#define GG 8

// ---------------- scratch (device globals: no allocation allowed) ----------------
__device__ float d_f[NN * DD];
__device__ unsigned short d_xh[NN * DD];   // fp16 copy of x
__device__ int   d_deg[NN];      // zeroed by k_final at end of each run (and BSS-zero at load)
__device__ int   d_start[NN];
__device__ int   d_rank[EE];     // per-edge rank within its dst segment (from hist atomic)
__device__ int   d_adj[EE];
__device__ float d_invdeg[NN];
__device__ float d_gsum[GG * DD];
__device__ float d_gsumsq[GG * DD];
__device__ int   d_cnt[GG];
__device__ int   d_counter;      // CSR allocation cursor
__device__ uint2 d_Wpk[8192];    // fp16 packed W fragments: [(op*8+c)*128 + d]*4 + q4

// ---------------- hist: degree histogram + ranks + zero stats + pack W + convert x->fp16 ----------------
__global__ void k_hist(const int* __restrict__ ei, const float* __restrict__ x,
                       const float* __restrict__ Wl, const float* __restrict__ Wr,
                       int e, int n) {
    int tidg = blockIdx.x * blockDim.x + threadIdx.x;
    int i0 = tidg * 4;
#pragma unroll
    for (int u = 0; u < 4; ++u) {
        int i = i0 + u;
        if (i < e) {
            int r = atomicAdd(&d_deg[ei[e + i]], 1);
            d_rank[i] = r;
        }
    }
    if (tidg < GG * DD) { d_gsum[tidg] = 0.f; d_gsumsq[tidg] = 0.f; }
    if (tidg < GG) d_cnt[tidg] = 0;
    if (tidg == 0) d_counter = 0;
    if (tidg < 8192) {
        int q4 = tidg & 3, d = (tidg >> 2) & 127, c = (tidg >> 9) & 7, op = tidg >> 12;
        const float* W = op ? Wr : Wl;
        int k0 = c * 16;
        float2 p0 = *(const float2*)(W + (size_t)d * DD + k0 + q4 * 2);
        float2 p1 = *(const float2*)(W + (size_t)d * DD + k0 + 8 + q4 * 2);
        __half2 h0 = __float22half2_rn(p0);
        __half2 h1 = __float22half2_rn(p1);
        uint2 o;
        o.x = *reinterpret_cast<unsigned*>(&h0);
        o.y = *reinterpret_cast<unsigned*>(&h1);
        d_Wpk[tidg] = o;
    }
    // convert x -> fp16 (grid-stride over float4 elements)
    int tot = n * 32;
    int gridT = gridDim.x * blockDim.x;
    for (int j = tidg; j < tot; j += gridT) {
        float4 v = ((const float4*)x)[j];
        __half2 h0 = __float22half2_rn(make_float2(v.x, v.y));
        __half2 h1 = __float22half2_rn(make_float2(v.z, v.w));
        uint2 o;
        o.x = *reinterpret_cast<unsigned*>(&h0);
        o.y = *reinterpret_cast<unsigned*>(&h1);
        ((uint2*)d_xh)[j] = o;
    }
}

// ---------------- single-pass scan: block scan + atomic block base (CSR order-free) ----------------
__global__ void k_scan(int n) {
    __shared__ int ws[8];
    __shared__ int base_s;
    int t = threadIdx.x, i = blockIdx.x * 256 + t;
    int lane = t & 31, w = t >> 5;

    int own = (i < n) ? d_deg[i] : 0;
    int v = own;
#pragma unroll
    for (int off = 1; off < 32; off <<= 1) {
        int u = __shfl_up_sync(0xffffffffu, v, off);
        if (lane >= off) v += u;
    }
    if (lane == 31) ws[w] = v;
    __syncthreads();
    if (w == 0) {
        int sv = (lane < 8) ? ws[lane] : 0;
#pragma unroll
        for (int off = 1; off < 8; off <<= 1) {
            int u = __shfl_up_sync(0xffffffffu, sv, off);
            if (lane >= off) sv += u;
        }
        if (lane < 8) ws[lane] = sv;       // inclusive warp-total scan
        if (lane == 7) base_s = atomicAdd(&d_counter, sv);  // block total
    }
    __syncthreads();
    int add = (w > 0) ? ws[w - 1] : 0;
    if (i < n) {
        int excl = v - own + add + base_s;
        d_start[i] = excl;
        d_invdeg[i] = 1.0f / fmaxf((float)own, 1.0f);
    }
}

// ---------------- fill adjacency: atomic-free (rank precomputed) + per-graph node counts ----------------
__global__ void k_fill(const int* __restrict__ ei, const int* __restrict__ batch, int e, int n) {
    int tidg = blockIdx.x * blockDim.x + threadIdx.x;
    int i0 = tidg * 4;
#pragma unroll
    for (int u = 0; u < 4; ++u) {
        int i = i0 + u;
        if (i < e) {
            int s = ei[i];
            int d = ei[e + i];
            int p = d_start[d] + d_rank[i];
            d_adj[p] = s;
        }
    }
    int key = (tidg < n) ? batch[tidg] : -1;
    unsigned m = __match_any_sync(0xffffffffu, key);
    int leader = __ffs(m) - 1;
    if ((int)(threadIdx.x & 31) == leader && key >= 0)
        atomicAdd(&d_cnt[key], __popc(m));
}

// ---------------- fused gather + tensor GEMM + GELU + stats ----------------
#define MMA_F16(c, a, b0v, b1v)                                            \
    asm volatile(                                                          \
        "mma.sync.aligned.m16n8k16.row.col.f32.f16.f16.f32 "               \
        "{%0,%1,%2,%3},{%4,%5,%6,%7},{%8,%9},{%0,%1,%2,%3};\n"             \
        : "+f"(c[0]), "+f"(c[1]), "+f"(c[2]), "+f"(c[3])                   \
        : "r"(a[0]), "r"(a[1]), "r"(a[2]), "r"(a[3]), "r"(b0v), "r"(b1v))

#define STRH 68   // agg smem row stride in u32 (64 + pad 4)

__global__ __launch_bounds__(256, 2) void k_gemm(
    const float* __restrict__ x, const float* __restrict__ bl,
    const int* __restrict__ batch, int n)
{
    __shared__ unsigned agg_h[64 * STRH];
    __shared__ float red_s[8][66];
    __shared__ float red_q[8][66];
    __shared__ int   bsm[64];
    __shared__ float bias_s[128];

    int t = threadIdx.x, wid = t >> 5, lane = t & 31;
    int r = lane >> 2, q4 = lane & 3;
    int wm = wid >> 1, wn = wid & 1;
    int n0 = blockIdx.x * 64;

    if (t < 64) bsm[t] = (n0 + t < n) ? batch[n0 + t] : -1;
    if (t < 128) bias_s[t] = bl[t];

    const uint2* xh2 = (const uint2*)d_xh;

    // ---- gather phase: warp wid gathers nodes wid*8 .. wid*8+7, fp16 rows, MLP=8 ----
#pragma unroll 1
    for (int u = 0; u < 8; ++u) {
        int ln = wid * 8 + u;
        int gn = n0 + ln;
        float4 a0 = make_float4(0.f, 0.f, 0.f, 0.f);
        float4 a1 = make_float4(0.f, 0.f, 0.f, 0.f);
        float inv = 0.f;
        if (gn < n) {
            int s0 = d_start[gn];
            int dg = d_deg[gn];
            inv = d_invdeg[gn];
            int j = 0;
            for (; j + 8 <= dg; j += 8) {
                int si[8];
#pragma unroll
                for (int k = 0; k < 8; ++k) si[k] = __ldg(&d_adj[s0 + j + k]);
                uint2 uv[8];
#pragma unroll
                for (int k = 0; k < 8; ++k) uv[k] = xh2[(size_t)si[k] * 32 + lane];
#pragma unroll
                for (int k = 0; k < 8; ++k) {
                    float2 f0 = __half22float2(*reinterpret_cast<__half2*>(&uv[k].x));
                    float2 f1 = __half22float2(*reinterpret_cast<__half2*>(&uv[k].y));
                    if (k & 1) { a1.x += f0.x; a1.y += f0.y; a1.z += f1.x; a1.w += f1.y; }
                    else       { a0.x += f0.x; a0.y += f0.y; a0.z += f1.x; a0.w += f1.y; }
                }
            }
#pragma unroll 4
            for (; j < dg; ++j) {
                int s = __ldg(&d_adj[s0 + j]);
                uint2 uv = xh2[(size_t)s * 32 + lane];
                float2 f0 = __half22float2(*reinterpret_cast<__half2*>(&uv.x));
                float2 f1 = __half22float2(*reinterpret_cast<__half2*>(&uv.y));
                a0.x += f0.x; a0.y += f0.y; a0.z += f1.x; a0.w += f1.y;
            }
        }
        __half2 p0 = __float22half2_rn(make_float2((a0.x + a1.x) * inv, (a0.y + a1.y) * inv));
        __half2 p1 = __float22half2_rn(make_float2((a0.z + a1.z) * inv, (a0.w + a1.w) * inv));
        uint2 o;
        o.x = *reinterpret_cast<unsigned*>(&p0);
        o.y = *reinterpret_cast<unsigned*>(&p1);
        *(uint2*)&agg_h[ln * STRH + lane * 2] = o;
    }
    __syncthreads();

    int row0 = n0 + wm * 16 + r;
    int row1 = row0 + 8;
    bool v0 = row0 < n, v1 = row1 < n;
    int rc0 = v0 ? row0 : 0, rc1 = v1 ? row1 : 0;

    float acc[8][4];
#pragma unroll
    for (int nt = 0; nt < 8; ++nt)
#pragma unroll
        for (int j = 0; j < 4; ++j) acc[nt][j] = 0.f;

    // ---- chunks 0..7: A from smem (packed half2, pre-scaled agg) ----
    int ai0 = (wm * 16 + r) * STRH + q4;
    int ai1 = (wm * 16 + r + 8) * STRH + q4;
#pragma unroll
    for (int cc = 0; cc < 8; ++cc) {
        unsigned ah[4];
        ah[0] = agg_h[ai0 + cc * 8];
        ah[1] = agg_h[ai1 + cc * 8];
        ah[2] = agg_h[ai0 + cc * 8 + 4];
        ah[3] = agg_h[ai1 + cc * 8 + 4];
#pragma unroll
        for (int nt = 0; nt < 8; ++nt) {
            uint2 B = d_Wpk[(cc * 128 + wn * 64 + nt * 8 + r) * 4 + q4];
            MMA_F16(acc[nt], ah, B.x, B.y);
        }
    }

    // ---- chunks 8..15: A direct from d_xh (already packed fp16) ----
    const unsigned* xh32 = (const unsigned*)d_xh;
    int xb0 = rc0 * 64 + q4;
    int xb1 = rc1 * 64 + q4;
#pragma unroll
    for (int cc = 0; cc < 8; ++cc) {
        unsigned ah[4];
        ah[0] = v0 ? xh32[xb0 + cc * 8]     : 0u;
        ah[1] = v1 ? xh32[xb1 + cc * 8]     : 0u;
        ah[2] = v0 ? xh32[xb0 + cc * 8 + 4] : 0u;
        ah[3] = v1 ? xh32[xb1 + cc * 8 + 4] : 0u;
#pragma unroll
        for (int nt = 0; nt < 8; ++nt) {
            uint2 B = d_Wpk[((cc + 8) * 128 + wn * 64 + nt * 8 + r) * 4 + q4];
            MMA_F16(acc[nt], ah, B.x, B.y);
        }
    }

    // bias + exact GELU
#pragma unroll
    for (int nt = 0; nt < 8; ++nt) {
        int d0 = wn * 64 + nt * 8 + q4 * 2;
        float bb0 = bias_s[d0], bb1 = bias_s[d0 + 1];
        acc[nt][0] += bb0; acc[nt][1] += bb1;
        acc[nt][2] += bb0; acc[nt][3] += bb1;
#pragma unroll
        for (int j = 0; j < 4; ++j) {
            float v = acc[nt][j];
            acc[nt][j] = 0.5f * v * (1.0f + erff(v * 0.70710678118654752f));
        }
    }

    // write f
#pragma unroll
    for (int nt = 0; nt < 8; ++nt) {
        int col = wn * 64 + nt * 8 + q4 * 2;
        if (v0) *(float2*)(d_f + (size_t)row0 * DD + col) = make_float2(acc[nt][0], acc[nt][1]);
        if (v1) *(float2*)(d_f + (size_t)row1 * DD + col) = make_float2(acc[nt][2], acc[nt][3]);
    }

    // per-graph sum / sumsq
    int last = min(63, n - 1 - n0);
    int glo = bsm[0], ghi = bsm[last];
    int g0r = bsm[wm * 16 + r];
    int g1r = bsm[wm * 16 + r + 8];
    for (int g = glo; g <= ghi; ++g) {
        float s[16], q[16];
#pragma unroll
        for (int i = 0; i < 16; ++i) { s[i] = 0.f; q[i] = 0.f; }
        if (g0r == g)
#pragma unroll
            for (int nt = 0; nt < 8; ++nt) {
                float a0 = acc[nt][0], a1 = acc[nt][1];
                s[nt * 2] += a0; s[nt * 2 + 1] += a1;
                q[nt * 2] += a0 * a0; q[nt * 2 + 1] += a1 * a1;
            }
        if (g1r == g)
#pragma unroll
            for (int nt = 0; nt < 8; ++nt) {
                float a2 = acc[nt][2], a3 = acc[nt][3];
                s[nt * 2] += a2; s[nt * 2 + 1] += a3;
                q[nt * 2] += a2 * a2; q[nt * 2 + 1] += a3 * a3;
            }
#pragma unroll
        for (int off = 4; off < 32; off <<= 1)
#pragma unroll
            for (int i = 0; i < 16; ++i) {
                s[i] += __shfl_xor_sync(0xffffffffu, s[i], off);
                q[i] += __shfl_xor_sync(0xffffffffu, q[i], off);
            }
        if (lane < 4)
#pragma unroll
            for (int nt = 0; nt < 8; ++nt) {
                red_s[wid][nt * 8 + lane * 2]     = s[nt * 2];
                red_s[wid][nt * 8 + lane * 2 + 1] = s[nt * 2 + 1];
                red_q[wid][nt * 8 + lane * 2]     = q[nt * 2];
                red_q[wid][nt * 8 + lane * 2 + 1] = q[nt * 2 + 1];
            }
        __syncthreads();
        if (t < 128) {
            int wn_ = t >> 6, dl = t & 63;
            float ts = 0.f, tq = 0.f;
#pragma unroll
            for (int wm_ = 0; wm_ < 4; ++wm_) {
                ts += red_s[wm_ * 2 + wn_][dl];
                tq += red_q[wm_ * 2 + wn_][dl];
            }
            atomicAdd(&d_gsum[g * DD + t], ts);
            atomicAdd(&d_gsumsq[g * DD + t], tq);
        }
        __syncthreads();
    }
}

// ---------------- final: per-block norm params + normalize + residual + re-zero d_deg ----------------
__global__ __launch_bounds__(512) void k_final(
    const float* __restrict__ x, const int* __restrict__ batch,
    const float* __restrict__ gw, const float* __restrict__ gb,
    const float* __restrict__ ms, float* __restrict__ out, int n)
{
    __shared__ float An_s[GG * DD];
    __shared__ float Bn_s[GG * DD];

    int t = threadIdx.x;
    int n0 = blockIdx.x * 128;
    int last = min(127, n - 1 - n0);
    int glo = batch[n0], ghi = batch[n0 + last];

    // re-zero degree counters for the next run (graph replay reuses state)
    if (t < 128 && n0 + t < n) d_deg[n0 + t] = 0;

    int np = (ghi - glo + 1) * DD;
    for (int i = t; i < np; i += 512) {
        int g = glo + (i >> 7), d = i & 127;
        int gi = g * DD + d;
        float c = fmaxf((float)d_cnt[g], 1.f);
        float mean = d_gsum[gi] / c;
        float m2 = d_gsumsq[gi] / c;
        float m = ms[d];
        float var = m2 - m * (2.f - m) * mean * mean;
        var = fmaxf(var, 0.f);
        float rstd = rsqrtf(var + 1e-5f);
        float A = gw[d] * rstd;
        An_s[gi] = A;
        Bn_s[gi] = gb[d] - m * mean * A;
    }
    __syncthreads();

#pragma unroll
    for (int p = 0; p < 8; ++p) {
        int flat = p * 512 + t;
        int nl = flat >> 5, c = flat & 31;
        int node = n0 + nl;
        if (node >= n) break;
        int g = batch[node];
        size_t i = (size_t)node * 32 + c;
        float4 f = ((const float4*)d_f)[i];
        float4 xv = ((const float4*)x)[i];
        float4 a = *(const float4*)&An_s[g * DD + c * 4];
        float4 b = *(const float4*)&Bn_s[g * DD + c * 4];
        float4 o;
        o.x = f.x * a.x + b.x + xv.x;
        o.y = f.y * a.y + b.y + xv.y;
        o.z = f.z * a.z + b.z + xv.z;
        o.w = f.w * a.w + b.w + xv.w;
        ((float4*)out)[i] = o;
    }
}

// ---------------- launch ----------------
extern "C" void kernel_launch(void* const* d_in, const int* in_sizes, int n_in,
                              void* d_out, int out_size) {
    const float* x     = (const float*)d_in[0];
    const int*   ei    = (const int*)d_in[1];
    const int*   batch = (const int*)d_in[2];
    const float* Wl  = (const float*)d_in[4];
    const float* bl  = (const float*)d_in[5];
    const float* Wr  = (const float*)d_in[6];
    const float* gw  = (const float*)d_in[7];
    const float* gb  = (const float*)d_in[8];
    const float* msc = (const float*)d_in[9];
    float* out = (float*)d_out;

    int n = in_sizes[0] / DD;
    int e = in_sizes[1] / 2;
    int nb = (n + 255) / 256;

    k_hist<<<(e / 4 + 255) / 256, 256>>>(ei, x, Wl, Wr, e, n);
    k_scan<<<nb, 256>>>(n);
    k_fill<<<(e / 4 + 255) / 256, 256>>>(ei, batch, e, n);
    k_gemm<<<(n + 63) / 64, 256>>>(x, bl, batch, n);
    k_final<<<(n + 127) / 128, 512>>>(x, batch, gw, gb, msc, out, n);
}